// round 1
// baseline (speedup 1.0000x reference)
#include <cuda_runtime.h>
#include <cstdint>

#define NCLS   10
#define NBINS  11          // 10 classes + dummy bin for mask==0
#define BLOCK  256
#define NGRID  (148 * 8)   // one full wave at 8 blocks/SM

// Global scratch accumulators (allocation-free scratch per harness rules)
__device__ float g_sum[NCLS];
__device__ float g_cnt[NCLS];

__global__ void zero_k() {
    int i = threadIdx.x;
    if (i < NCLS) { g_sum[i] = 0.0f; g_cnt[i] = 0.0f; }
}

// Accumulate one element into this thread's private bin row.
// bins layout: [NBINS][BLOCK] float2  ->  row stride = BLOCK*8 = 2048 bytes.
// Address per lane = base + key*2048 + tid*8 ; within a 16-lane phase the
// bank index is (2*tid) mod 32 regardless of key -> conflict-free LDS.64/STS.64.
__device__ __forceinline__ void acc_one(float ov, float tv, int mv, float2* row_tid) {
    float e  = ov - tv;
    float sq = e * e;
    int cls  = (int)tv;                 // targets are exact small integers
    int key  = (mv == 1) ? cls : NCLS;  // invalid pixels -> dummy bin
    float2* p = row_tid + key * BLOCK;

    unsigned long long v = *reinterpret_cast<unsigned long long*>(p);
    unsigned long long inc;
    // pack {sq, 1.0f} into one 64-bit reg pair, then one packed f32x2 add
    asm("mov.b64 %0, {%1, %2};" : "=l"(inc) : "f"(sq), "f"(1.0f));
    asm("add.rn.f32x2 %0, %1, %2;" : "=l"(v) : "l"(v), "l"(inc));
    *reinterpret_cast<unsigned long long*>(p) = v;
}

__global__ __launch_bounds__(BLOCK) void hist_k(
    const float* __restrict__ outs,
    const float* __restrict__ tgts,
    const int*   __restrict__ mask,
    int n)
{
    __shared__ float2 bins[NBINS][BLOCK];
    const int tid = threadIdx.x;

    #pragma unroll
    for (int c = 0; c < NBINS; c++) bins[c][tid] = make_float2(0.0f, 0.0f);
    __syncthreads();

    float2* row_tid = &bins[0][tid];

    const int n4 = n >> 2;
    const float4* __restrict__ o4 = reinterpret_cast<const float4*>(outs);
    const float4* __restrict__ t4 = reinterpret_cast<const float4*>(tgts);
    const int4*   __restrict__ m4 = reinterpret_cast<const int4*>(mask);

    const int stride = NGRID * BLOCK;
    for (int i = blockIdx.x * BLOCK + tid; i < n4; i += stride) {
        float4 ov = o4[i];
        float4 tv = t4[i];
        int4   mv = m4[i];
        acc_one(ov.x, tv.x, mv.x, row_tid);
        acc_one(ov.y, tv.y, mv.y, row_tid);
        acc_one(ov.z, tv.z, mv.z, row_tid);
        acc_one(ov.w, tv.w, mv.w, row_tid);
    }

    // tail (n not divisible by 4) — handled by block 0 only
    if (blockIdx.x == 0) {
        int i = (n4 << 2) + tid;
        if (i < n) acc_one(outs[i], tgts[i], mask[i], row_tid);
    }
    __syncthreads();

    // block tree-reduction over tid for each class row
    for (int s = BLOCK / 2; s > 0; s >>= 1) {
        if (tid < s) {
            #pragma unroll
            for (int c = 0; c < NCLS; c++) {   // dummy bin discarded
                float2 a = bins[c][tid];
                float2 b = bins[c][tid + s];
                bins[c][tid] = make_float2(a.x + b.x, a.y + b.y);
            }
        }
        __syncthreads();
    }

    if (tid < NCLS) {
        atomicAdd(&g_sum[tid], bins[tid][0].x);
        atomicAdd(&g_cnt[tid], bins[tid][0].y);
    }
}

__global__ void fin_k(float* __restrict__ out, int out_size) {
    int i = threadIdx.x;
    // out is poisoned; clear everything we own
    for (int j = i; j < out_size; j += 32) out[j] = 0.0f;
    __syncwarp();

    __shared__ float le[NCLS];
    if (i < NCLS) {
        float s = g_sum[i];
        float n = g_cnt[i];
        float v = (n > 0.0f) ? (s / fmaxf(n, 1.0f)) : 0.0f;
        le[i] = v;
        if (1 + i < out_size)            out[1 + i] = v;          // loss_each
        if (1 + NCLS + i < out_size)     out[1 + NCLS + i] = n;   // class_n
    }
    __syncwarp();
    if (i == 0) {
        float loss = 0.0f;
        #pragma unroll
        for (int c = 0; c < NCLS; c++) loss += 0.1f * le[c];
        out[0] = loss;
    }
}

extern "C" void kernel_launch(void* const* d_in, const int* in_sizes, int n_in,
                              void* d_out, int out_size) {
    const float* outs = (const float*)d_in[0];
    const float* tgts = (const float*)d_in[1];
    const int*   mask = (const int*)d_in[2];
    float* out = (float*)d_out;
    int n = in_sizes[0];

    zero_k<<<1, 32>>>();
    hist_k<<<NGRID, BLOCK>>>(outs, tgts, mask, n);
    fin_k<<<1, 32>>>(out, out_size);
}